// round 17
// baseline (speedup 1.0000x reference)
#include <cuda_runtime.h>
#include <stdint.h>

#define B       8
#define NH      778
#define VOBJ    40000
#define NTOT    (B * NH)          // 6224
#define GD      16                // grid cells per axis
#define NC      (GD * GD * GD)    // 4096 cells per batch
#define CS      (0.1f / GD)       // 6.25 mm
#define INVCS   (GD / 0.1f)

#define CBX     157               // count/scatter blocks per batch (157*256 >= 40000)
#define CNBLK   (CBX * B)         // 1256

#define QWARPS  8
#define QBX     ((NH + QWARPS - 1) / QWARPS)   // 98
#define NQB     (QBX * B)                      // 784

__constant__ int c_contact_idx[10] = {745, 317, 444, 556, 673, 95, 182, 234, 279, 320};

// zero-initialized at load; all state self-resets each run -> replay-safe
__device__ int    g_cnt[B * NC];
__device__ int    g_start[B * (NC + 1)];
__device__ int    g_fill[B * NC];
__device__ float4 g_pts[B * VOBJ];
__device__ float  g_red_f[NQB * 3];
__device__ int    g_red_i[NQB * 2];
__device__ int    g_ticket;      // query finalize
__device__ int    g_ticket2;     // count->scan handoff

__device__ __forceinline__ void cell_of(float x, float y, float z,
                                        int& cx, int& cy, int& cz) {
    cx = min(GD - 1, max(0, (int)(x * INVCS)));
    cy = min(GD - 1, max(0, (int)(y * INVCS)));
    cz = min(GD - 1, max(0, (int)(z * INVCS)));
}

// K1: histogram points into cells; LAST 8 blocks (ticket) each scan one batch
__global__ __launch_bounds__(256) void count_scan_kernel(const float* __restrict__ obj)
{
    const int j = blockIdx.x * 256 + threadIdx.x;
    const int b = blockIdx.y;
    const int t = threadIdx.x;

    if (j < VOBJ) {
        const float* p = obj + ((size_t)b * VOBJ + j) * 3;
        int cx, cy, cz;
        cell_of(p[0], p[1], p[2], cx, cy, cz);
        atomicAdd(&g_cnt[b * NC + (cz * GD + cy) * GD + cx], 1);
    }
    __syncthreads();

    __shared__ int s_tk;
    if (t == 0) {
        __threadfence();                       // publish our counts
        s_tk = atomicAdd(&g_ticket2, 1);
    }
    __syncthreads();
    const int tk = s_tk;
    if (tk < CNBLK - 8) return;
    __threadfence();                           // acquire all counts

    // this block scans batch sb
    const int sb = tk - (CNBLK - 8);
    const int lane = t & 31, wid = t >> 5;
    __shared__ int sc[NC];                     // 16 KB

    #pragma unroll
    for (int i = t; i < NC; i += 256) {
        sc[i] = g_cnt[sb * NC + i];
        g_cnt[sb * NC + i] = 0;                // reset for next replay
    }
    __syncthreads();

    int c[16], sum = 0;
    #pragma unroll
    for (int i = 0; i < 16; i++) { c[i] = sc[t * 16 + i]; sum += c[i]; }

    int incl = sum;
    #pragma unroll
    for (int off = 1; off < 32; off <<= 1) {
        int v = __shfl_up_sync(0xffffffffu, incl, off);
        if (lane >= off) incl += v;
    }
    __shared__ int wsum[8], wexc[8];
    if (lane == 31) wsum[wid] = incl;
    __syncthreads();
    if (t == 0) {
        int run = 0;
        #pragma unroll
        for (int w = 0; w < 8; w++) { wexc[w] = run; run += wsum[w]; }
    }
    __syncthreads();

    int run = wexc[wid] + (incl - sum);
    #pragma unroll
    for (int i = 0; i < 16; i++) { sc[t * 16 + i] = run; run += c[i]; }
    __syncthreads();

    #pragma unroll
    for (int i = t; i < NC; i += 256) {
        int v = sc[i];
        g_start[sb * (NC + 1) + i] = v;
        g_fill[sb * NC + i] = v;
    }
    if (t == 255) g_start[sb * (NC + 1) + NC] = VOBJ;
    if (tk == CNBLK - 1 && t == 0) g_ticket2 = 0;   // self-reset
}

// K2: scatter points into cell-sorted order (cell recomputed; no cellid array)
__global__ __launch_bounds__(256) void scatter_kernel(const float* __restrict__ obj)
{
    const int j = blockIdx.x * 256 + threadIdx.x;
    const int b = blockIdx.y;
    if (j >= VOBJ) return;
    const float* p = obj + ((size_t)b * VOBJ + j) * 3;
    float x = p[0], y = p[1], z = p[2];
    int cx, cy, cz;
    cell_of(x, y, z, cx, cy, cz);
    const int cell = (cz * GD + cy) * GD + cx;
    const int pos  = atomicAdd(&g_fill[b * NC + cell], 1);
    g_pts[b * VOBJ + pos] = make_float4(x, y, z, 0.f);
}

// K3: exact 1-NN, one warp per query; single range epoch + seeded row pruning
__global__ __launch_bounds__(QWARPS * 32) void query_kernel(
    const float* __restrict__ hand, float* __restrict__ out)
{
    const int t    = threadIdx.x;
    const int lane = t & 31;
    const int w    = t >> 5;
    const int b    = blockIdx.y;
    const int h    = blockIdx.x * QWARPS + w;
    const unsigned FULL = 0xffffffffu;

    float d = 0.f;

    if (h < NH) {
        const float* hp = hand + ((size_t)b * NH + h) * 3;
        const float px = hp[0], py = hp[1], pz = hp[2];
        int cx, cy, cz;
        cell_of(px, py, pz, cx, cy, cz);
        const int sb = b * (NC + 1);
        const float4* pts = g_pts + (size_t)b * VOBJ;

        // r=1 cube geometry
        const int x0 = max(0, cx - 1), x1 = min(GD - 1, cx + 1);
        const int y0 = max(0, cy - 1), y1 = min(GD - 1, cy + 1);
        const int z0 = max(0, cz - 1), z1 = min(GD - 1, cz + 1);
        const int ny = y1 - y0 + 1;
        const int nrows = ny * (z1 - z0 + 1);        // <= 9

        // ONE epoch: all row ranges + center range + per-row y/z box dist
        int   s = 0, e = 0;
        float rowd2 = 3.4e38f;
        if (lane < nrows) {
            const int zz = z0 + lane / ny;
            const int yy = y0 + lane % ny;
            const int row = sb + (zz * GD + yy) * GD;
            s = g_start[row + x0];
            e = g_start[row + x1 + 1];               // contiguous x-run
            float ry0 = yy * CS, rz0 = zz * CS;
            float dy = fmaxf(fmaxf(ry0 - py, py - (ry0 + CS)), 0.f);
            float dz = fmaxf(fmaxf(rz0 - pz, pz - (rz0 + CS)), 0.f);
            rowd2 = fmaf(dy, dy, dz * dz);
        }
        const int crow = sb + (cz * GD + cy) * GD + cx;
        const int cs0 = g_start[crow];               // broadcast loads (same addr)
        const int ce0 = g_start[crow + 1];

        // seed: center cell
        float best = 3.4e38f;
        for (int k = cs0 + lane; k < ce0; k += 32) {
            float4 qq = pts[k];
            float dx = px - qq.x, dy = py - qq.y, dz = pz - qq.z;
            best = fminf(best, fmaf(dx, dx, fmaf(dy, dy, dz * dz)));
        }
        #pragma unroll
        for (int off = 16; off > 0; off >>= 1)
            best = fminf(best, __shfl_xor_sync(FULL, best, off));

        const float lim = best * 1.0001f + 1e-12f;

        // row pass with pruning (center row rowd2=0 -> always scanned)
        for (int rr = 0; rr < nrows; rr++) {
            const float rd = __shfl_sync(FULL, rowd2, rr);
            if (rd > lim) continue;                  // provably can't beat seed
            const int ss = __shfl_sync(FULL, s, rr);
            const int ee = __shfl_sync(FULL, e, rr);
            for (int k = ss + lane; k < ee; k += 32) {
                float4 qq = pts[k];
                float dx = px - qq.x, dy = py - qq.y, dz = pz - qq.z;
                best = fminf(best, fmaf(dx, dx, fmaf(dy, dy, dz * dz)));
            }
        }
        #pragma unroll
        for (int off = 16; off > 0; off >>= 1)
            best = fminf(best, __shfl_xor_sync(FULL, best, off));

        // exactness bound for r=1
        bool done;
        {
            float bd = 3.4e38f;
            if (x0 > 0)      bd = fminf(bd, px - x0 * CS);
            if (x1 < GD - 1) bd = fminf(bd, (x1 + 1) * CS - px);
            if (y0 > 0)      bd = fminf(bd, py - y0 * CS);
            if (y1 < GD - 1) bd = fminf(bd, (y1 + 1) * CS - py);
            if (z0 > 0)      bd = fminf(bd, pz - z0 * CS);
            if (z1 < GD - 1) bd = fminf(bd, (z1 + 1) * CS - pz);
            bd = fmaxf(bd - 2e-6f, 0.f);
            done = (best <= bd * bd) ||
                   (x0 == 0 && x1 == GD - 1 && y0 == 0 && y1 == GD - 1 &&
                    z0 == 0 && z1 == GD - 1);
        }

        // rare expansion: generic full scan, r = 2..GD
        if (!done) {
            for (int r = 2; r <= GD; r++) {
                const int ex0 = max(0, cx - r), ex1 = min(GD - 1, cx + r);
                const int ey0 = max(0, cy - r), ey1 = min(GD - 1, cy + r);
                const int ez0 = max(0, cz - r), ez1 = min(GD - 1, cz + r);
                const int eny = ey1 - ey0 + 1;
                const int enrows = eny * (ez1 - ez0 + 1);
                best = 3.4e38f;
                for (int base = 0; base < enrows; base += 32) {
                    const int li = base + lane;
                    int ss2 = 0, ee2 = 0;
                    if (li < enrows) {
                        const int zz = ez0 + li / eny;
                        const int yy = ey0 + li % eny;
                        const int row = sb + (zz * GD + yy) * GD;
                        ss2 = g_start[row + ex0];
                        ee2 = g_start[row + ex1 + 1];
                    }
                    const int cnt = min(enrows - base, 32);
                    for (int rr = 0; rr < cnt; rr++) {
                        const int aa = __shfl_sync(FULL, ss2, rr);
                        const int bb = __shfl_sync(FULL, ee2, rr);
                        for (int k = aa + lane; k < bb; k += 32) {
                            float4 qq = pts[k];
                            float dx = px - qq.x, dy = py - qq.y, dz = pz - qq.z;
                            best = fminf(best, fmaf(dx, dx, fmaf(dy, dy, dz * dz)));
                        }
                    }
                }
                #pragma unroll
                for (int off = 16; off > 0; off >>= 1)
                    best = fminf(best, __shfl_xor_sync(FULL, best, off));

                const bool all = (ex0 == 0) && (ex1 == GD - 1) && (ey0 == 0) &&
                                 (ey1 == GD - 1) && (ez0 == 0) && (ez1 == GD - 1);
                if (all) break;
                float bd = 3.4e38f;
                if (ex0 > 0)      bd = fminf(bd, px - ex0 * CS);
                if (ex1 < GD - 1) bd = fminf(bd, (ex1 + 1) * CS - px);
                if (ey0 > 0)      bd = fminf(bd, py - ey0 * CS);
                if (ey1 < GD - 1) bd = fminf(bd, (ey1 + 1) * CS - py);
                if (ez0 > 0)      bd = fminf(bd, pz - ez0 * CS);
                if (ez1 < GD - 1) bd = fminf(bd, (ez1 + 1) * CS - pz);
                bd = fmaxf(bd - 2e-6f, 0.f);
                if (best <= bd * bd) break;
            }
        }
        d = sqrtf(fmaxf(best, 0.f));
    }

    // per-warp stats, cross-warp combine, ticket finalize
    __shared__ float sf[3][QWARPS];
    __shared__ int   si[2][QWARPS];
    if (lane == 0) {
        float sum_d = 0.f, pen = 0.f, att = 0.f;
        int   pc = 0, ac = 0;
        if (h < NH) {
            sum_d = d;
            if (d < 0.005f) { float tt = 0.005f - d; pen = tt * tt; pc = 1; }
            bool isc = false;
            #pragma unroll
            for (int j = 0; j < 10; j++) isc |= (h == c_contact_idx[j]);
            if (isc && d > 0.005f && d < 0.01f) { att = d * d; ac = 1; }
        }
        sf[0][w] = sum_d; sf[1][w] = pen; sf[2][w] = att;
        si[0][w] = pc;    si[1][w] = ac;
    }
    __syncthreads();

    __shared__ int s_last;
    if (t == 0) {
        float a = 0.f, c = 0.f, e = 0.f;
        int   p = 0, qq = 0;
        #pragma unroll
        for (int i = 0; i < QWARPS; i++) {
            a += sf[0][i]; c += sf[1][i]; e += sf[2][i];
            p += si[0][i]; qq += si[1][i];
        }
        const int slot = b * QBX + blockIdx.x;
        g_red_f[slot * 3 + 0] = a;
        g_red_f[slot * 3 + 1] = c;
        g_red_f[slot * 3 + 2] = e;
        g_red_i[slot * 2 + 0] = p;
        g_red_i[slot * 2 + 1] = qq;
        __threadfence();
        int ticket = atomicAdd(&g_ticket, 1);
        s_last = (ticket == NQB - 1) ? 1 : 0;
    }
    __syncthreads();
    if (!s_last) return;
    __threadfence();

    float a = 0.f, c = 0.f, e = 0.f;
    int   p = 0, qq = 0;
    for (int r = t; r < NQB; r += QWARPS * 32) {   // fixed order -> deterministic
        a += g_red_f[r * 3 + 0];
        c += g_red_f[r * 3 + 1];
        e += g_red_f[r * 3 + 2];
        p += g_red_i[r * 2 + 0];
        qq += g_red_i[r * 2 + 1];
    }
    #pragma unroll
    for (int off = 16; off > 0; off >>= 1) {
        a += __shfl_down_sync(FULL, a, off);
        c += __shfl_down_sync(FULL, c, off);
        e += __shfl_down_sync(FULL, e, off);
        p += __shfl_down_sync(FULL, p, off);
        qq += __shfl_down_sync(FULL, qq, off);
    }
    __shared__ float ff[3][QWARPS];
    __shared__ int   ii[2][QWARPS];
    if (lane == 0) {
        ff[0][w] = a; ff[1][w] = c; ff[2][w] = e;
        ii[0][w] = p; ii[1][w] = qq;
    }
    __syncthreads();
    if (t == 0) {
        float ta = 0.f, tc = 0.f, te = 0.f;
        int   tp = 0, tq = 0;
        #pragma unroll
        for (int i = 0; i < QWARPS; i++) {
            ta += ff[0][i]; tc += ff[1][i]; te += ff[2][i];
            tp += ii[0][i]; tq += ii[1][i];
        }
        float pen_loss = (tp > 0) ? tc / (float)tp : 0.f;
        float att_loss = (tq > 0) ? te / (float)tq : 0.f;
        out[0] = 100.f * pen_loss + 10.f * att_loss;
        out[1] = pen_loss;
        out[2] = att_loss;
        out[3] = ta / (float)NTOT;
        out[4] = (float)tq;   // num_contacts
        out[5] = (float)tp;   // num_penetrations
        g_ticket = 0;         // self-reset for next graph replay
    }
}

extern "C" void kernel_launch(void* const* d_in, const int* in_sizes, int n_in,
                              void* d_out, int out_size)
{
    const float* hand = (const float*)d_in[0];  // [8, 778, 3] f32
    const float* obj  = (const float*)d_in[1];  // [8, 40000, 3] f32
    float* out = (float*)d_out;

    dim3 pg(CBX, B);
    count_scan_kernel<<<pg, 256>>>(obj);
    scatter_kernel   <<<pg, 256>>>(obj);
    query_kernel     <<<dim3(QBX, B), QWARPS * 32>>>(hand, out);
    (void)in_sizes; (void)n_in; (void)out_size;
}